// round 2
// baseline (speedup 1.0000x reference)
#include <cuda_runtime.h>
#include <cstdint>

#define NROWS 8192
#define L2E 1.44269504088896340736f

// ---------------- scratch ----------------
__device__ __align__(16) unsigned g_mask[NROWS * 256];   // 8 MB bitmask
__device__ __align__(16) float g_h[4 * NROWS * 64];      // per-head h = x@Wh
__device__ __align__(16) float g_xcat[NROWS * 256];      // concat LR(head outputs)
__device__ __align__(16) float g_h2[NROWS * 16];         // xcat@Wo
__device__ __align__(16) float g_f1[5 * NROWS];          // f1 * log2e per layer
__device__ __align__(16) float g_f2[5 * NROWS];          // f2 * log2e per layer
__device__ __align__(16) float g_m[5 * NROWS];           // row max (log2 domain)
__device__ __align__(16) float g_part[8 * NROWS * 16];   // final-layer partials
__device__ __align__(16) float g_partZ[8 * NROWS];

// ---------------- helpers ----------------
__device__ __forceinline__ float ex2f(float x) {
    float r; asm("ex2.approx.ftz.f32 %0, %1;" : "=f"(r) : "f"(x)); return r;
}
__device__ __forceinline__ unsigned long long pk2(float a, float b) {
    unsigned long long r; asm("mov.b64 %0, {%1, %2};" : "=l"(r) : "f"(a), "f"(b)); return r;
}
__device__ __forceinline__ void up2(unsigned long long v, float& a, float& b) {
    asm("mov.b64 {%0, %1}, %2;" : "=f"(a), "=f"(b) : "l"(v));
}
__device__ __forceinline__ void fma2(unsigned long long& d, unsigned long long a, unsigned long long b) {
    asm("fma.rn.f32x2 %0, %1, %2, %0;" : "+l"(d) : "l"(a), "l"(b));
}
__device__ __forceinline__ void lds2u64(const float* p, unsigned long long& a, unsigned long long& b) {
    unsigned sa = (unsigned)__cvta_generic_to_shared(p);
    asm volatile("ld.shared.v2.u64 {%0, %1}, [%2];" : "=l"(a), "=l"(b) : "r"(sa));
}

// ---------------- 1) pack adjacency ----------------
__global__ void __launch_bounds__(256) pack_adj_kernel(const int* __restrict__ adj) {
    const int lane = threadIdx.x & 31;
    const int wid = (blockIdx.x * blockDim.x + threadIdx.x) >> 5;
    const int nWarps = (gridDim.x * blockDim.x) >> 5;
    for (int w = wid; w < NROWS * 256; w += nWarps) {
        int v = adj[(size_t)w * 32 + lane];
        unsigned b = __ballot_sync(0xffffffffu, v > 0);
        if (lane == 0) g_mask[w] = b;
    }
}

// ---------------- 2) h = x @ Wh[head] (8192x512x64) ----------------
__global__ void __launch_bounds__(256) gemm64_kernel(const float* __restrict__ X,
                                                     const float* __restrict__ WhAll) {
    const int head = blockIdx.y;
    const float* W = WhAll + head * (512 * 64);
    float* C = g_h + head * (NROWS * 64);
    const int r0 = blockIdx.x * 64;
    const int tid = threadIdx.x;
    __shared__ float4 As4[512];  // [32 k][64 m]
    __shared__ float4 Bs4[512];  // [32 k][64 n]
    float* As = (float*)As4;
    const int tr = tid >> 4, tc = tid & 15;
    const int lm = tid & 63, kg = tid >> 6;
    float acc[4][4];
#pragma unroll
    for (int i = 0; i < 4; i++)
#pragma unroll
        for (int j = 0; j < 4; j++) acc[i][j] = 0.f;

    for (int kt = 0; kt < 512; kt += 32) {
        __syncthreads();
        const float* xb = X + (size_t)(r0 + lm) * 512 + kt + kg * 8;
        float4 a0 = ((const float4*)xb)[0];
        float4 a1 = ((const float4*)xb)[1];
        As[(kg * 8 + 0) * 64 + lm] = a0.x; As[(kg * 8 + 1) * 64 + lm] = a0.y;
        As[(kg * 8 + 2) * 64 + lm] = a0.z; As[(kg * 8 + 3) * 64 + lm] = a0.w;
        As[(kg * 8 + 4) * 64 + lm] = a1.x; As[(kg * 8 + 5) * 64 + lm] = a1.y;
        As[(kg * 8 + 6) * 64 + lm] = a1.z; As[(kg * 8 + 7) * 64 + lm] = a1.w;
        const float4* wsrc = (const float4*)(W + kt * 64);
        Bs4[tid] = wsrc[tid];
        Bs4[tid + 256] = wsrc[tid + 256];
        __syncthreads();
#pragma unroll
        for (int kk = 0; kk < 32; kk++) {
            float4 av = As4[kk * 16 + tr];
            float4 bv = Bs4[kk * 16 + tc];
            float aa[4] = {av.x, av.y, av.z, av.w};
            float bb[4] = {bv.x, bv.y, bv.z, bv.w};
#pragma unroll
            for (int i = 0; i < 4; i++)
#pragma unroll
                for (int j = 0; j < 4; j++) acc[i][j] += aa[i] * bb[j];
        }
    }
#pragma unroll
    for (int i = 0; i < 4; i++) {
        float4 o = make_float4(acc[i][0], acc[i][1], acc[i][2], acc[i][3]);
        *(float4*)(C + (size_t)(r0 + tr * 4 + i) * 64 + tc * 4) = o;
    }
}

// ---------------- 3) f1/f2 (log2-scaled) ----------------
__global__ void __launch_bounds__(256) f1f2_heads_kernel(const float* __restrict__ ah) {
    const int head = blockIdx.y;
    const float* H = g_h + head * (NROWS * 64);
    const float* a = ah + head * 128;
    const int lane = threadIdx.x & 31;
    const int row = blockIdx.x * 8 + (threadIdx.x >> 5);
    float h0 = H[row * 64 + lane], h1 = H[row * 64 + 32 + lane];
    float s1 = h0 * a[lane] + h1 * a[32 + lane];
    float s2 = h0 * a[64 + lane] + h1 * a[96 + lane];
#pragma unroll
    for (int off = 16; off; off >>= 1) {
        s1 += __shfl_xor_sync(0xffffffffu, s1, off);
        s2 += __shfl_xor_sync(0xffffffffu, s2, off);
    }
    if (lane == 0) {
        g_f1[head * NROWS + row] = s1 * L2E;
        g_f2[head * NROWS + row] = s2 * L2E;
    }
}

__global__ void __launch_bounds__(256) f1f2_final_kernel(const float* __restrict__ ao) {
    const int lane = threadIdx.x & 31;
    const int row = blockIdx.x * 8 + (threadIdx.x >> 5);
    float s1 = 0.f, s2 = 0.f;
    if (lane < 16) {
        float h = g_h2[row * 16 + lane];
        s1 = h * ao[lane];
        s2 = h * ao[16 + lane];
    }
#pragma unroll
    for (int off = 16; off; off >>= 1) {
        s1 += __shfl_xor_sync(0xffffffffu, s1, off);
        s2 += __shfl_xor_sync(0xffffffffu, s2, off);
    }
    if (lane == 0) {
        g_f1[4 * NROWS + row] = s1 * L2E;
        g_f2[4 * NROWS + row] = s2 * L2E;
    }
}

// ---------------- 4) masked row max (monotone LR shortcut) ----------------
__global__ void __launch_bounds__(256) rowmax_kernel(int layer0) {
    const int layer = layer0 + blockIdx.y;
    const float* f1 = g_f1 + layer * NROWS;
    const float* f2 = g_f2 + layer * NROWS;
    float* mo = g_m + layer * NROWS;
    __shared__ float4 f2s4[2048];
    float* f2s = (float*)f2s4;
    const int tid = threadIdx.x;
    const float4* src = (const float4*)f2;
#pragma unroll
    for (int v = 0; v < 8; v++) f2s4[tid + 256 * v] = src[tid + 256 * v];
    __syncthreads();
    const int warp = tid >> 5, lane = tid & 31;
    for (int it = 0; it < 4; it++) {
        const int row = blockIdx.x * 32 + it * 8 + warp;
        float mx = -3.0e38f;
#pragma unroll
        for (int k = 0; k < 8; k++) {
            const int w = lane + 32 * k;
            unsigned bits = g_mask[row * 256 + w];
#pragma unroll
            for (int t = 0; t < 32; t++) {
                float v = ((bits >> t) & 1u) ? f2s[w * 32 + t] : -3.0e38f;
                mx = fmaxf(mx, v);
            }
        }
#pragma unroll
        for (int off = 16; off; off >>= 1) mx = fmaxf(mx, __shfl_xor_sync(0xffffffffu, mx, off));
        if (lane == 0) {
            float s = f1[row] + mx;
            mo[row] = fmaxf(s, 0.2f * s);  // leaky_relu commutes with *L2E>0
        }
    }
}

// ---------------- 5) head attention -> xcat ----------------
__global__ void __launch_bounds__(128) attn_heads_kernel() {
    const int head = blockIdx.y;
    const float* __restrict__ H = g_h + head * (NROWS * 64);
    const float* __restrict__ f1 = g_f1 + head * NROWS;
    const float* __restrict__ f2 = g_f2 + head * NROWS;
    const float* __restrict__ mv = g_m + head * NROWS;
    const int r0 = blockIdx.x * 128;
    const int tid = threadIdx.x;
    __shared__ float4 Hs4[2048];  // 128x64 f32
    __shared__ float f2s[128];
    __shared__ uint4 ms4[128];
    float* Hs = (float*)Hs4;
    unsigned* msw = (unsigned*)ms4;
    const int row = r0 + tid;
    const float f1i = f1[row];
    const float mi = mv[row];
    unsigned long long acc[32];
#pragma unroll
    for (int q = 0; q < 32; q++) acc[q] = 0ull;
    float z = 0.f;

    for (int j0 = 0; j0 < NROWS; j0 += 128) {
        __syncthreads();
        const float4* src = (const float4*)(H + (size_t)j0 * 64);
#pragma unroll
        for (int v = 0; v < 16; v++) Hs4[tid + 128 * v] = src[tid + 128 * v];
        f2s[tid] = f2[j0 + tid];
        const int wb = j0 >> 5;
#pragma unroll
        for (int v = 0; v < 4; v++) {
            int idx = tid + 128 * v;
            msw[idx] = g_mask[(r0 + (idx >> 2)) * 256 + wb + (idx & 3)];
        }
        __syncthreads();
        uint4 mwv = ms4[tid];
        unsigned bw[4] = {mwv.x, mwv.y, mwv.z, mwv.w};
#pragma unroll
        for (int w = 0; w < 4; w++) {
            unsigned bits = bw[w];
#pragma unroll 4
            for (int t = 0; t < 32; t++) {
                const int jj = w * 32 + t;
                float sL = f1i + f2s[jj];
                float eL = fmaxf(sL, 0.2f * sL);
                float px = ex2f(eL - mi);
                float p = ((bits >> t) & 1u) ? px : 0.f;
                z += p;
                unsigned long long p2 = pk2(p, p);
                const float* hp = Hs + jj * 64;
#pragma unroll
                for (int q = 0; q < 16; q++) {
                    unsigned long long h0, h1;
                    lds2u64(hp + q * 4, h0, h1);
                    fma2(acc[2 * q], p2, h0);
                    fma2(acc[2 * q + 1], p2, h1);
                }
            }
        }
    }
    float inv = 1.f / z;
    float* outp = g_xcat + (size_t)row * 256 + head * 64;
#pragma unroll
    for (int q = 0; q < 32; q++) {
        float a, b;
        up2(acc[q], a, b);
        a *= inv; b *= inv;
        a = fmaxf(a, 0.01f * a);
        b = fmaxf(b, 0.01f * b);
        outp[2 * q] = a;
        outp[2 * q + 1] = b;
    }
}

// ---------------- 6) h2 = xcat @ Wo (8192x256x16) ----------------
__global__ void __launch_bounds__(128) gemm2_kernel(const float* __restrict__ Wo) {
    __shared__ float Ws[256 * 16];
    const int tid = threadIdx.x;
    for (int i = tid; i < 4096; i += 128) Ws[i] = Wo[i];
    __syncthreads();
    const int row = blockIdx.x * 128 + tid;
    const float* xr = g_xcat + (size_t)row * 256;
    float acc[16];
#pragma unroll
    for (int j = 0; j < 16; j++) acc[j] = 0.f;
    for (int k = 0; k < 256; k += 4) {
        float4 xv = *(const float4*)(xr + k);
#pragma unroll
        for (int j = 0; j < 16; j++) {
            acc[j] += xv.x * Ws[(k + 0) * 16 + j];
            acc[j] += xv.y * Ws[(k + 1) * 16 + j];
            acc[j] += xv.z * Ws[(k + 2) * 16 + j];
            acc[j] += xv.w * Ws[(k + 3) * 16 + j];
        }
    }
#pragma unroll
    for (int j = 0; j < 16; j++) g_h2[row * 16 + j] = acc[j];
}

// ---------------- 7) final attention (j-split partials) ----------------
__global__ void __launch_bounds__(128) attn_final_kernel() {
    const int chunk = blockIdx.y;  // 0..7, each 1024 j
    const float* __restrict__ f1 = g_f1 + 4 * NROWS;
    const float* __restrict__ f2 = g_f2 + 4 * NROWS;
    const float* __restrict__ mv = g_m + 4 * NROWS;
    const int r0 = blockIdx.x * 128;
    const int tid = threadIdx.x;
    __shared__ float4 Hs4[512];  // 128x16 f32
    __shared__ float f2s[128];
    __shared__ uint4 ms4[128];
    float* Hs = (float*)Hs4;
    unsigned* msw = (unsigned*)ms4;
    const int row = r0 + tid;
    const float f1i = f1[row];
    const float mi = mv[row];
    unsigned long long acc[8];
#pragma unroll
    for (int q = 0; q < 8; q++) acc[q] = 0ull;
    float z = 0.f;

    for (int j0 = chunk * 1024; j0 < chunk * 1024 + 1024; j0 += 128) {
        __syncthreads();
        const float4* src = (const float4*)(g_h2 + (size_t)j0 * 16);
#pragma unroll
        for (int v = 0; v < 4; v++) Hs4[tid + 128 * v] = src[tid + 128 * v];
        f2s[tid] = f2[j0 + tid];
        const int wb = j0 >> 5;
#pragma unroll
        for (int v = 0; v < 4; v++) {
            int idx = tid + 128 * v;
            msw[idx] = g_mask[(r0 + (idx >> 2)) * 256 + wb + (idx & 3)];
        }
        __syncthreads();
        uint4 mwv = ms4[tid];
        unsigned bw[4] = {mwv.x, mwv.y, mwv.z, mwv.w};
#pragma unroll
        for (int w = 0; w < 4; w++) {
            unsigned bits = bw[w];
#pragma unroll 4
            for (int t = 0; t < 32; t++) {
                const int jj = w * 32 + t;
                float sL = f1i + f2s[jj];
                float eL = fmaxf(sL, 0.2f * sL);
                float px = ex2f(eL - mi);
                float p = ((bits >> t) & 1u) ? px : 0.f;
                z += p;
                unsigned long long p2 = pk2(p, p);
                const float* hp = Hs + jj * 16;
#pragma unroll
                for (int q = 0; q < 4; q++) {
                    unsigned long long h0, h1;
                    lds2u64(hp + q * 4, h0, h1);
                    fma2(acc[2 * q], p2, h0);
                    fma2(acc[2 * q + 1], p2, h1);
                }
            }
        }
    }
    float* pp = g_part + ((size_t)chunk * NROWS + row) * 16;
#pragma unroll
    for (int q = 0; q < 8; q++) {
        float a, b;
        up2(acc[q], a, b);
        pp[2 * q] = a;
        pp[2 * q + 1] = b;
    }
    g_partZ[chunk * NROWS + row] = z;
}

// ---------------- 8) reduce partials -> output ----------------
__global__ void __launch_bounds__(256) reduce_kernel(float* __restrict__ out) {
    const int idx = blockIdx.x * 256 + threadIdx.x;  // 8192*16
    const int row = idx >> 4;
    float s = 0.f, z = 0.f;
#pragma unroll
    for (int c = 0; c < 8; c++) {
        s += g_part[((size_t)c * NROWS + row) * 16 + (idx & 15)];
        z += g_partZ[c * NROWS + row];
    }
    out[idx] = s / z;
}

extern "C" void kernel_launch(void* const* d_in, const int* in_sizes, int n_in,
                              void* d_out, int out_size) {
    const float* x   = (const float*)d_in[0];
    const int*   adj = (const int*)d_in[1];
    const float* Wh  = (const float*)d_in[2];
    const float* ah  = (const float*)d_in[3];
    const float* Wo  = (const float*)d_in[4];
    const float* ao  = (const float*)d_in[5];
    float* out = (float*)d_out;

    pack_adj_kernel<<<2048, 256>>>(adj);
    gemm64_kernel<<<dim3(128, 4), 256>>>(x, Wh);
    f1f2_heads_kernel<<<dim3(1024, 4), 256>>>(ah);
    rowmax_kernel<<<dim3(256, 4), 256>>>(0);
    attn_heads_kernel<<<dim3(64, 4), 128>>>();
    gemm2_kernel<<<64, 128>>>(Wo);
    f1f2_final_kernel<<<1024, 256>>>(ao);
    rowmax_kernel<<<dim3(256, 1), 256>>>(4);
    attn_final_kernel<<<dim3(64, 8), 128>>>();
    reduce_kernel<<<512, 256>>>(out);
}